// round 14
// baseline (speedup 1.0000x reference)
#include <cuda_runtime.h>
#include <math.h>
#include <stdint.h>

#define HID   128
#define TIN   512
#define TTOT  514
#define NGROUP 4
#define NTHR  256
#define GRID_N 144     // 4 groups x (1 l0-hh + 4 hh + 4 ih) x 4 CTAs
#define CSIZE 4

// smem float offsets
#define OFF_BAR  0        // 1 mbarrier (8 floats)
#define OFF_HH   8        // hh: HOWN [2][128][8]=2048 ; ih: HBEL [128][8]
#define OFF_G    2056     // partials [128 rows][18 float2] = 4608 floats
#define OFF_PIH  6664     // staged ih sums [128][8] = 1024
#define OFF_X    7688     // layer0 x [512][8] = 4096
#define OFF_BIAS 11784    // 128
#define OFF_WX   11912    // 128
#define SMEM_BYTES (12048 * 4)

__device__ float g_h[4][TTOT][NGROUP][HID][8];
__device__ float g_pih[4][TTOT][NGROUP][4][128][8];
__device__ float g_xpred[2][NGROUP][8];
__device__ int   g_cnt[NGROUP][4][TTOT];
__device__ int   g_pflag[NGROUP][4][4];
__device__ int   g_xdone[NGROUP][2];

__global__ void zero_flags_kernel() {
    int i = blockIdx.x * blockDim.x + threadIdx.x;
    if (i < NGROUP * 4 * TTOT) ((int*)g_cnt)[i] = 0;
    if (i < NGROUP * 4 * 4) ((int*)g_pflag)[i] = 0;
    if (i < NGROUP * 2) ((int*)g_xdone)[i] = 0;
}

__device__ __forceinline__ int ld_acq(const int* p) {
    int v; asm volatile("ld.acquire.gpu.global.b32 %0,[%1];" : "=r"(v) : "l"(p)); return v;
}
__device__ __forceinline__ void red_rel(int* p) {
    asm volatile("red.release.gpu.global.add.s32 [%0],1;" :: "l"(p));
}
__device__ __forceinline__ float2 ffma2(float w, float2 h, float2 acc) {
    union { float2 f; unsigned long long u; } A, B, C, D;
    A.f = make_float2(w, w); B.f = h; C.f = acc;
    asm("fma.rn.f32x2 %0, %1, %2, %3;" : "=l"(D.u) : "l"(A.u), "l"(B.u), "l"(C.u));
    return D.f;
}
__device__ __forceinline__ float sigm(float v) {
    return __fdividef(1.0f, 1.0f + __expf(-v));
}
__device__ __forceinline__ float tanh_fast(float v) {
    return 1.0f - __fdividef(2.0f, __expf(2.0f * v) + 1.0f);
}
__device__ __forceinline__ float act1(float i, float f, float g, float o, float& c) {
    i = sigm(i); f = sigm(f); g = tanh_fast(g); o = sigm(o);
    c = f * c + i * g;
    return o * tanh_fast(c);
}
__device__ __forceinline__ uint32_t mapa_u32(uint32_t a, uint32_t r) {
    uint32_t d; asm("mapa.shared::cluster.u32 %0,%1,%2;" : "=r"(d) : "r"(a), "r"(r)); return d;
}
__device__ __forceinline__ void st_cluster_f2(uint32_t a, float2 v) {
    asm volatile("st.shared::cluster.v2.f32 [%0],{%1,%2};" :: "r"(a), "f"(v.x), "f"(v.y) : "memory");
}
__device__ __forceinline__ void mbar_init(uint32_t a, uint32_t n) {
    asm volatile("mbarrier.init.shared.b64 [%0],%1;" :: "r"(a), "r"(n) : "memory");
}
__device__ __forceinline__ void mbar_arrive_rel(uint32_t a) {
    asm volatile("mbarrier.arrive.release.cluster.shared::cluster.b64 _,[%0];" :: "r"(a) : "memory");
}
__device__ __forceinline__ void bar_wait(uint32_t a, uint32_t parity) {
    uint32_t done;
    do {
        asm volatile(
            "{\n\t.reg .pred p;\n\t"
            "mbarrier.try_wait.parity.acquire.cluster.shared::cta.b64 p,[%1],%2;\n\t"
            "selp.b32 %0,1,0,p;\n\t}"
            : "=r"(done) : "r"(a), "r"(parity) : "memory");
    } while (!done);
}

// register-weight 4-k body: wreg[J4] row rp, wreg[8+J4] row rp+64
#define GEMV_R(J4)                                                             \
    {                                                                          \
        float4 wa = wreg[J4], wb = wreg[8 + (J4)];                             \
        _Pragma("unroll")                                                      \
        for (int jj = 0; jj < 4; jj++) {                                       \
            float w1v = (jj == 0) ? wa.x : (jj == 1) ? wa.y : (jj == 2) ? wa.z : wa.w; \
            float w2v = (jj == 0) ? wb.x : (jj == 1) ? wb.y : (jj == 2) ? wb.z : wb.w; \
            float4 h0 = h4[((J4) * 4 + jj) * 2];                               \
            float4 h1 = h4[((J4) * 4 + jj) * 2 + 1];                           \
            float2 p01 = make_float2(h0.x, h0.y), p23 = make_float2(h0.z, h0.w); \
            float2 p45 = make_float2(h1.x, h1.y), p67 = make_float2(h1.z, h1.w); \
            aA0 = ffma2(w1v, p01, aA0); aA1 = ffma2(w1v, p23, aA1);            \
            aA2 = ffma2(w1v, p45, aA2); aA3 = ffma2(w1v, p67, aA3);            \
            aB0 = ffma2(w2v, p01, aB0); aB1 = ffma2(w2v, p23, aB1);            \
            aB2 = ffma2(w2v, p45, aB2); aB3 = ffma2(w2v, p67, aB3);            \
        }                                                                      \
    }

__global__ void __launch_bounds__(NTHR, 1)
lstm_main(const float* __restrict__ x,    const float* __restrict__ Wih0,
          const float* __restrict__ Wihr, const float* __restrict__ Whh,
          const float* __restrict__ bih,  const float* __restrict__ bhh,
          const float* __restrict__ W1,   const float* __restrict__ b1,
          const float* __restrict__ W2,   const float* __restrict__ b2,
          float* __restrict__ out)
{
    extern __shared__ float smem[];
    const uint32_t sbase = (uint32_t)__cvta_generic_to_shared(smem);
    const int tid  = threadIdx.x;
    const int bid  = blockIdx.x;
    const int rank = bid & 3;
    const int cid  = bid >> 2;
    const int group = cid / 9;
    const int c     = cid % 9;
    const bool is_ih = (c >= 5);
    const int layer  = is_ih ? (c - 4) : c;
    const int b0 = group * 8;

    const int kc = tid >> 6;          // K-quarter (32 k)
    const int rp = tid & 63;          // rows rp, rp+64
    const int au = tid >> 2, abp = tid & 3;
    const uint32_t bar = sbase + OFF_BAR * 4;
    float2* sP = (float2*)&smem[OFF_G];

    // ---- weights into registers: 2 rows x 32 k ----
    float4 wreg[16];
    {
        const float* wsrc = is_ih ? (Wihr + (size_t)(layer - 1) * 512 * HID)
                                  : (Whh + (size_t)layer * 512 * HID);
        int RA = (rp >> 5) * HID + rank * 32 + (rp & 31);
        int RB = RA + 2 * HID;
        #pragma unroll
        for (int j = 0; j < 8; j++) {
            wreg[j]     = *(const float4*)&wsrc[RA * HID + kc * 32 + j * 4];
            wreg[8 + j] = *(const float4*)&wsrc[RB * HID + kc * 32 + j * 4];
        }
    }
    if (!is_ih) {
        if (tid == 0) mbar_init(sbase + OFF_BAR * 4, 4);   // 3 remote + 1 self
        for (int i = tid; i < 2048; i += NTHR) smem[OFF_HH + i] = 0.0f;
        if (tid < 128) {
            int R = layer * 512 + (tid >> 5) * HID + rank * 32 + (tid & 31);
            smem[OFF_BIAS + tid] = bih[R] + bhh[R];
            if (layer == 0) smem[OFF_WX + tid] = Wih0[R];
        }
        if (layer == 0)
            for (int i = tid; i < TIN * 8; i += NTHR) {
                int t = i >> 3, bb = i & 7;
                smem[OFF_X + t * 8 + bb] = x[(b0 + bb) * TIN + t];
            }
    }
    __syncthreads();
    asm volatile("barrier.cluster.arrive.aligned;" ::: "memory");
    asm volatile("barrier.cluster.wait.aligned;" ::: "memory");

    if (is_ih) {
        // ================= ih CTA =================
        for (int t = 0; t < TTOT; t++) {
            if (tid == 0) { const int* pc = &g_cnt[group][layer - 1][t];
                            while (ld_acq(pc) < 4) {} }
            __syncthreads();
            ((float4*)&smem[OFF_HH])[tid] =
                ((const float4*)&g_h[layer - 1][t][group][0][0])[tid];
            __syncthreads();
            float2 aA0, aA1, aA2, aA3, aB0, aB1, aB2, aB3;
            aA0 = aA1 = aA2 = aA3 = make_float2(0.f, 0.f);
            aB0 = aB1 = aB2 = aB3 = aA0;
            const float4* h4 = (const float4*)&smem[OFF_HH + kc * 32 * 8];
            #pragma unroll
            for (int j4 = 0; j4 < 8; j4++) GEMV_R(j4)
            {
                float2* pp = sP + rp * 18 + kc * 4;
                *(float4*)(pp)     = make_float4(aA0.x, aA0.y, aA1.x, aA1.y);
                *(float4*)(pp + 2) = make_float4(aA2.x, aA2.y, aA3.x, aA3.y);
                float2* pq = pp + 64 * 18;
                *(float4*)(pq)     = make_float4(aB0.x, aB0.y, aB1.x, aB1.y);
                *(float4*)(pq + 2) = make_float4(aB2.x, aB2.y, aB3.x, aB3.y);
            }
            __syncthreads();
            {   // reduce 4 partials, publish: row = tid>>1, half = tid&1
                int row = tid >> 1, half = tid & 1;
                const float2* pr = sP + row * 18 + half * 2;
                float2 sA = pr[0], sB = pr[1];
                #pragma unroll
                for (int q = 1; q < 4; q++) {
                    float2 vA = pr[q * 4], vB = pr[q * 4 + 1];
                    sA.x += vA.x; sA.y += vA.y; sB.x += vB.x; sB.y += vB.y;
                }
                *(float4*)&g_pih[layer - 1][t][group][rank][row][half * 4] =
                    make_float4(sA.x, sA.y, sB.x, sB.y);
            }
            __syncthreads();
            if (tid == 0) red_rel(&g_pflag[group][layer - 1][rank]);
        }
        return;
    }

    // ================= hh CTA =================
    float2 cst = make_float2(0.0f, 0.0f);
    for (int t = 0; t < TTOT; t++) {
        const int par = t & 1;

        // prefetch ih sums (slack path)
        float4 pih = make_float4(0.f, 0.f, 0.f, 0.f);
        if (layer > 0) {
            const int* pf = &g_pflag[group][layer - 1][rank];
            while (ld_acq(pf) < t + 1) {}
            pih = ((const float4*)&g_pih[layer - 1][t][group][rank][0][0])[tid];
        }

        float2 aA0, aA1, aA2, aA3, aB0, aB1, aB2, aB3;
        if (kc == 0) {
            float bA = smem[OFF_BIAS + rp], bB = smem[OFF_BIAS + rp + 64];
            aA0 = aA1 = aA2 = aA3 = make_float2(bA, bA);
            aB0 = aB1 = aB2 = aB3 = make_float2(bB, bB);
        } else {
            aA0 = aA1 = aA2 = aA3 = make_float2(0.f, 0.f);
            aB0 = aB1 = aB2 = aB3 = aA0;
        }

        if (layer == 0 && kc == 0) {
            float4 xlo, xhi;
            if (t < TIN) {
                const float4* xp = (const float4*)&smem[OFF_X + t * 8];
                xlo = xp[0]; xhi = xp[1];
            } else {
                if (tid == 0) { while (ld_acq(&g_xdone[group][t - TIN]) < 1) {} }
                asm volatile("bar.sync 2, 64;" ::: "memory");
                const float4* xp = (const float4*)&g_xpred[t - TIN][group][0];
                xlo = xp[0]; xhi = xp[1];
            }
            float wxA = smem[OFF_WX + rp], wxB = smem[OFF_WX + rp + 64];
            float2 q01 = make_float2(xlo.x, xlo.y), q23 = make_float2(xlo.z, xlo.w);
            float2 q45 = make_float2(xhi.x, xhi.y), q67 = make_float2(xhi.z, xhi.w);
            aA0 = ffma2(wxA, q01, aA0); aA1 = ffma2(wxA, q23, aA1);
            aA2 = ffma2(wxA, q45, aA2); aA3 = ffma2(wxA, q67, aA3);
            aB0 = ffma2(wxB, q01, aB0); aB1 = ffma2(wxB, q23, aB1);
            aB2 = ffma2(wxB, q45, aB2); aB3 = ffma2(wxB, q67, aB3);
        }

        if (t > 0) bar_wait(bar, (t - 1) & 1);

        {
            const float4* h4 = (const float4*)&smem[OFF_HH + (par ^ 1) * 1024 + kc * 32 * 8];
            #pragma unroll
            for (int j4 = 0; j4 < 8; j4++) GEMV_R(j4)
        }
        {
            float2* pp = sP + rp * 18 + kc * 4;
            *(float4*)(pp)     = make_float4(aA0.x, aA0.y, aA1.x, aA1.y);
            *(float4*)(pp + 2) = make_float4(aA2.x, aA2.y, aA3.x, aA3.y);
            float2* pq = pp + 64 * 18;
            *(float4*)(pq)     = make_float4(aB0.x, aB0.y, aB1.x, aB1.y);
            *(float4*)(pq + 2) = make_float4(aB2.x, aB2.y, aB3.x, aB3.y);
        }
        if (layer > 0) ((float4*)&smem[OFF_PIH])[tid] = pih;
        __syncthreads();

        // ---- act + push (tid<128); others proceed to next wait ----
        if (tid < 128) {
            float2 gt[4];
            #pragma unroll
            for (int g = 0; g < 4; g++) {
                int row = g * 32 + au;
                const float2* pr = sP + row * 18 + abp;
                float2 s = pr[0];
                #pragma unroll
                for (int q = 1; q < 4; q++) { float2 v = pr[q * 4]; s.x += v.x; s.y += v.y; }
                if (layer > 0) {
                    float2 v = *(const float2*)&smem[OFF_PIH + row * 8 + abp * 2];
                    s.x += v.x; s.y += v.y;
                }
                gt[g] = s;
            }
            float2 ho;
            ho.x = act1(gt[0].x, gt[1].x, gt[2].x, gt[3].x, cst.x);
            ho.y = act1(gt[0].y, gt[1].y, gt[2].y, gt[3].y, cst.y);
            int uo = rank * 32 + au;
            *(float2*)&smem[OFF_HH + par * 1024 + uo * 8 + abp * 2] = ho;
            uint32_t hoff = sbase + (uint32_t)(OFF_HH + par * 1024 + uo * 8 + abp * 2) * 4;
            #pragma unroll
            for (int j = 0; j < CSIZE; j++)
                if (j != rank) st_cluster_f2(mapa_u32(hoff, j), ho);
            if (layer < 4)
                *(float2*)&g_h[layer][t][group][uo][abp * 2] = ho;
            asm volatile("bar.sync 3, 128;" ::: "memory");
            if (tid == 0) {
                #pragma unroll
                for (int j = 0; j < CSIZE; j++) mbar_arrive_rel(mapa_u32(bar, j));
                if (layer < 4) red_rel(&g_cnt[group][layer][t]);
            }
        }

        // ---- head (layer4 rank0, boundary steps) ----
        if (layer == 4 && rank == 0 && t >= 511) {
            int m = t - 511;
            bar_wait(bar, t & 1);
            const float* h4h = &smem[OFF_HH + par * 1024];
            float* z2 = &smem[OFF_G];
            {
                int j = tid & 127, bh = tid >> 7;   // bh 0..1
                float2 acc0 = make_float2(b1[j], b1[j]);
                float2 acc1 = acc0;
                for (int k = 0; k < HID; k++) {
                    float w = W1[k * HID + j];
                    float2 h0 = *(const float2*)&h4h[k * 8 + bh * 2];
                    float2 h1 = *(const float2*)&h4h[k * 8 + 4 + bh * 2];
                    acc0.x += w * fmaxf(h0.x, 0.0f); acc0.y += w * fmaxf(h0.y, 0.0f);
                    acc1.x += w * fmaxf(h1.x, 0.0f); acc1.y += w * fmaxf(h1.y, 0.0f);
                }
                z2[(2 * bh)     * 128 + j] = fmaxf(acc0.x, 0.0f);
                z2[(2 * bh + 1) * 128 + j] = fmaxf(acc0.y, 0.0f);
                z2[(4 + 2 * bh)     * 128 + j] = fmaxf(acc1.x, 0.0f);
                z2[(4 + 2 * bh + 1) * 128 + j] = fmaxf(acc1.y, 0.0f);
            }
            __syncthreads();
            if (tid < 128) {
                int b = tid >> 4, oo = tid & 15;
                float s = b2[oo];
                #pragma unroll 8
                for (int k = 0; k < HID; k++) s += z2[b * 128 + k] * W2[k * 16 + oo];
                if (m == 2) {
                    out[(b0 + b) * 18 + 2 + oo] = s;
                } else if (oo == 15) {
                    out[(b0 + b) * 18 + m] = s;
                    g_xpred[m][group][b] = s;
                }
            }
            __syncthreads();
            if (m < 2 && tid == 0) red_rel(&g_xdone[group][m]);
        }
    }

    asm volatile("barrier.cluster.arrive.aligned;" ::: "memory");
    asm volatile("barrier.cluster.wait.aligned;" ::: "memory");
}

extern "C" void kernel_launch(void* const* d_in, const int* in_sizes, int n_in,
                              void* d_out, int out_size) {
    const float* x    = (const float*)d_in[0];
    const float* Wih0 = (const float*)d_in[2];
    const float* Wihr = (const float*)d_in[3];
    const float* Whh  = (const float*)d_in[4];
    const float* bih  = (const float*)d_in[5];
    const float* bhh  = (const float*)d_in[6];
    const float* W1   = (const float*)d_in[7];
    const float* b1   = (const float*)d_in[8];
    const float* W2   = (const float*)d_in[9];
    const float* b2   = (const float*)d_in[10];
    float* out = (float*)d_out;

    static bool attr_set = false;
    if (!attr_set) {
        cudaFuncSetAttribute(lstm_main, cudaFuncAttributeMaxDynamicSharedMemorySize, SMEM_BYTES);
        attr_set = true;
    }

    zero_flags_kernel<<<17, 512>>>();

    cudaLaunchConfig_t cfg = {};
    cfg.gridDim = dim3(GRID_N, 1, 1);
    cfg.blockDim = dim3(NTHR, 1, 1);
    cfg.dynamicSmemBytes = SMEM_BYTES;
    cfg.stream = 0;
    cudaLaunchAttribute attrs[1];
    attrs[0].id = cudaLaunchAttributeClusterDimension;
    attrs[0].val.clusterDim.x = CSIZE;
    attrs[0].val.clusterDim.y = 1;
    attrs[0].val.clusterDim.z = 1;
    cfg.attrs = attrs;
    cfg.numAttrs = 1;
    cudaLaunchKernelEx(&cfg, lstm_main, x, Wih0, Wihr, Whh, bih, bhh,
                       W1, b1, W2, b2, out);
}

// round 16
// speedup vs baseline: 1.0389x; 1.0389x over previous
#include <cuda_runtime.h>
#include <math.h>
#include <stdint.h>

#define HID   128
#define TIN   512
#define TTOT  514
#define NGROUP 4
#define NTHR  512
#define GRID_N 144     // 4 groups x (1 l0-hh + 4 hh + 4 ih) x 4 CTAs
#define CSIZE 4
#define PRE_LAST 506   // last step index allowed as a prefetch TARGET (t+1 <= 506)

// smem float offsets
#define OFF_BAR  0
#define OFF_W    8        // 128 rows x stride 132
#define OFF_HH   16904    // hh: HOWN [2][128][8]=2048 ; ih: double-buffered HBEL [2][128][8]
#define OFF_G    18952    // partials [128 rows][34 float2] = 8704 floats
#define OFF_PIH  27656    // staged ih sums [128][8] = 1024
#define OFF_X    28680    // layer0 x [512][8] = 4096
#define OFF_BIAS 32776    // 128
#define OFF_WX   32904    // 128
#define SMEM_BYTES (33032 * 4)

__device__ float g_h[4][TTOT][NGROUP][HID][8];
__device__ float g_pih[4][TTOT][NGROUP][4][128][8];
__device__ float g_xpred[2][NGROUP][8];
__device__ int   g_cnt[NGROUP][4][TTOT];
__device__ int   g_pflag[NGROUP][4][4];
__device__ int   g_xdone[NGROUP][2];

__global__ void zero_flags_kernel() {
    int i = blockIdx.x * blockDim.x + threadIdx.x;
    if (i < NGROUP * 4 * TTOT) ((int*)g_cnt)[i] = 0;
    if (i < NGROUP * 4 * 4) ((int*)g_pflag)[i] = 0;
    if (i < NGROUP * 2) ((int*)g_xdone)[i] = 0;
}

__device__ __forceinline__ int ld_acq(const int* p) {
    int v; asm volatile("ld.acquire.gpu.global.b32 %0,[%1];" : "=r"(v) : "l"(p)); return v;
}
__device__ __forceinline__ void red_rel(int* p) {
    asm volatile("red.release.gpu.global.add.s32 [%0],1;" :: "l"(p));
}
__device__ __forceinline__ float2 ffma2(float w, float2 h, float2 acc) {
    union { float2 f; unsigned long long u; } A, B, C, D;
    A.f = make_float2(w, w); B.f = h; C.f = acc;
    asm("fma.rn.f32x2 %0, %1, %2, %3;" : "=l"(D.u) : "l"(A.u), "l"(B.u), "l"(C.u));
    return D.f;
}
__device__ __forceinline__ float sigm(float v) {
    return __fdividef(1.0f, 1.0f + __expf(-v));
}
__device__ __forceinline__ float tanh_fast(float v) {
    return 1.0f - __fdividef(2.0f, __expf(2.0f * v) + 1.0f);
}
__device__ __forceinline__ float act1(float i, float f, float g, float o, float& c) {
    i = sigm(i); f = sigm(f); g = tanh_fast(g); o = sigm(o);
    c = f * c + i * g;
    return o * tanh_fast(c);
}
__device__ __forceinline__ uint32_t mapa_u32(uint32_t a, uint32_t r) {
    uint32_t d; asm("mapa.shared::cluster.u32 %0,%1,%2;" : "=r"(d) : "r"(a), "r"(r)); return d;
}
__device__ __forceinline__ void st_cluster_f2(uint32_t a, float2 v) {
    asm volatile("st.shared::cluster.v2.f32 [%0],{%1,%2};" :: "r"(a), "f"(v.x), "f"(v.y) : "memory");
}
__device__ __forceinline__ void mbar_init(uint32_t a, uint32_t n) {
    asm volatile("mbarrier.init.shared.b64 [%0],%1;" :: "r"(a), "r"(n) : "memory");
}
__device__ __forceinline__ void mbar_arrive_rel(uint32_t a) {
    asm volatile("mbarrier.arrive.release.cluster.shared::cluster.b64 _,[%0];" :: "r"(a) : "memory");
}
__device__ __forceinline__ void bar_wait(uint32_t a, uint32_t parity) {
    uint32_t done;
    do {
        asm volatile(
            "{\n\t.reg .pred p;\n\t"
            "mbarrier.try_wait.parity.acquire.cluster.shared::cta.b64 p,[%1],%2;\n\t"
            "selp.b32 %0,1,0,p;\n\t}"
            : "=r"(done) : "r"(a), "r"(parity) : "memory");
    } while (!done);
}

#define GEMV_J4(J4)                                                            \
    {                                                                          \
        float4 wa = wA4[J4], wb = wB4[J4];                                     \
        _Pragma("unroll")                                                      \
        for (int jj = 0; jj < 4; jj++) {                                       \
            float w1v = (jj == 0) ? wa.x : (jj == 1) ? wa.y : (jj == 2) ? wa.z : wa.w; \
            float w2v = (jj == 0) ? wb.x : (jj == 1) ? wb.y : (jj == 2) ? wb.z : wb.w; \
            float4 h0 = h4[((J4) * 4 + jj) * 2];                               \
            float4 h1 = h4[((J4) * 4 + jj) * 2 + 1];                           \
            float2 p01 = make_float2(h0.x, h0.y), p23 = make_float2(h0.z, h0.w); \
            float2 p45 = make_float2(h1.x, h1.y), p67 = make_float2(h1.z, h1.w); \
            aA0 = ffma2(w1v, p01, aA0); aA1 = ffma2(w1v, p23, aA1);            \
            aA2 = ffma2(w1v, p45, aA2); aA3 = ffma2(w1v, p67, aA3);            \
            aB0 = ffma2(w2v, p01, aB0); aB1 = ffma2(w2v, p23, aB1);            \
            aB2 = ffma2(w2v, p45, aB2); aB3 = ffma2(w2v, p67, aB3);            \
        }                                                                      \
    }

__global__ void __launch_bounds__(NTHR, 1)
lstm_main(const float* __restrict__ x,    const float* __restrict__ Wih0,
          const float* __restrict__ Wihr, const float* __restrict__ Whh,
          const float* __restrict__ bih,  const float* __restrict__ bhh,
          const float* __restrict__ W1,   const float* __restrict__ b1,
          const float* __restrict__ W2,   const float* __restrict__ b2,
          float* __restrict__ out)
{
    extern __shared__ float smem[];
    const uint32_t sbase = (uint32_t)__cvta_generic_to_shared(smem);
    const int tid  = threadIdx.x;
    const int bid  = blockIdx.x;
    const int rank = bid & 3;
    const int cid  = bid >> 2;
    const int group = cid / 9;
    const int c     = cid % 9;
    const bool is_ih = (c >= 5);
    const int layer  = is_ih ? (c - 4) : c;
    const int b0 = group * 8;

    // ---- weight staging ----
    {
        const float* wsrc = is_ih ? (Wihr + (size_t)(layer - 1) * 512 * HID)
                                  : (Whh + (size_t)layer * 512 * HID);
        for (int i = tid; i < 128 * 128; i += NTHR) {
            int r = i >> 7, k = i & 127;
            int R = (r >> 5) * HID + rank * 32 + (r & 31);
            smem[OFF_W + r * 132 + k] = wsrc[R * HID + k];
        }
    }
    if (!is_ih) {
        if (tid == 0) mbar_init(sbase + OFF_BAR * 4, 3);
        for (int i = tid; i < 2048; i += NTHR) smem[OFF_HH + i] = 0.0f;
        if (tid < 128) {
            int R = layer * 512 + (tid >> 5) * HID + rank * 32 + (tid & 31);
            smem[OFF_BIAS + tid] = bih[R] + bhh[R];
            if (layer == 0) smem[OFF_WX + tid] = Wih0[R];
        }
        if (layer == 0)
            for (int i = tid; i < TIN * 8; i += NTHR) {
                int t = i >> 3, bb = i & 7;
                smem[OFF_X + t * 8 + bb] = x[(b0 + bb) * TIN + t];
            }
    }
    __syncthreads();
    asm volatile("barrier.cluster.arrive.aligned;" ::: "memory");
    asm volatile("barrier.cluster.wait.aligned;" ::: "memory");

    const int kc = tid >> 6;
    const int rp = tid & 63;
    const int au = tid >> 2, abp = tid & 3;
    const uint32_t bar = sbase + OFF_BAR * 4;
    float2* sP = (float2*)&smem[OFF_G];

    if (is_ih) {
        // ========== ih CTA: pipelined for t+1 <= PRE_LAST, plain after ==========
        if (tid == 0) { while (ld_acq(&g_cnt[group][layer - 1][0]) < 4) {} }
        __syncthreads();
        if (tid < 256)
            ((float4*)&smem[OFF_HH])[tid] =
                ((const float4*)&g_h[layer - 1][0][group][0][0])[tid];
        __syncthreads();

        for (int t = 0; t < TTOT; t++) {
            const int cur = t & 1;
            // boundary steps (t >= PRE_LAST+1): plain stage-then-compute
            if (t > PRE_LAST) {
                if (tid == 0) { while (ld_acq(&g_cnt[group][layer - 1][t]) < 4) {} }
                __syncthreads();
                if (tid < 256)
                    ((float4*)&smem[OFF_HH + cur * 1024])[tid] =
                        ((const float4*)&g_h[layer - 1][t][group][0][0])[tid];
                __syncthreads();
            }
            // prefetch h_below(t+1) (feedback-free region only)
            float4 pre = make_float4(0.f, 0.f, 0.f, 0.f);
            const bool pre_ok = (t + 1 <= PRE_LAST);
            if (pre_ok) {
                if (tid == 0) { while (ld_acq(&g_cnt[group][layer - 1][t + 1]) < 4) {} }
                __syncthreads();
                if (tid < 256)
                    pre = ((const float4*)&g_h[layer - 1][t + 1][group][0][0])[tid];
            }
            float2 aA0, aA1, aA2, aA3, aB0, aB1, aB2, aB3;
            aA0 = aA1 = aA2 = aA3 = make_float2(0.f, 0.f);
            aB0 = aB1 = aB2 = aB3 = aA0;
            const float4* wA4 = (const float4*)&smem[OFF_W + rp * 132 + kc * 16];
            const float4* wB4 = (const float4*)&smem[OFF_W + (rp + 64) * 132 + kc * 16];
            const float4* h4  = (const float4*)&smem[OFF_HH + cur * 1024 + kc * 16 * 8];
            #pragma unroll
            for (int j4 = 0; j4 < 4; j4++) GEMV_J4(j4)
            {
                float2* pp = sP + rp * 34 + kc * 4;
                *(float4*)(pp)     = make_float4(aA0.x, aA0.y, aA1.x, aA1.y);
                *(float4*)(pp + 2) = make_float4(aA2.x, aA2.y, aA3.x, aA3.y);
                float2* pq = pp + 64 * 34;
                *(float4*)(pq)     = make_float4(aB0.x, aB0.y, aB1.x, aB1.y);
                *(float4*)(pq + 2) = make_float4(aB2.x, aB2.y, aB3.x, aB3.y);
            }
            __syncthreads();
            {
                int row = tid >> 2, slot = tid & 3;
                const float2* pr = sP + row * 34 + slot;
                float2 s = pr[0];
                #pragma unroll
                for (int q = 1; q < 8; q++) { float2 v = pr[q * 4]; s.x += v.x; s.y += v.y; }
                *(float2*)&g_pih[layer - 1][t][group][rank][row][slot * 2] = s;
            }
            if (pre_ok && tid < 256)
                ((float4*)&smem[OFF_HH + (cur ^ 1) * 1024])[tid] = pre;
            __syncthreads();
            if (tid == 0) red_rel(&g_pflag[group][layer - 1][rank]);
        }
        return;
    }

    // ================= hh CTA (identical to R13) =================
    float2 cst = make_float2(0.0f, 0.0f);
    for (int t = 0; t < TTOT; t++) {
        const int par = t & 1;

        float4 pih = make_float4(0.f, 0.f, 0.f, 0.f);
        if (layer > 0) {
            const int* pf = &g_pflag[group][layer - 1][rank];
            while (ld_acq(pf) < t + 1) {}
            if (tid < 256)
                pih = ((const float4*)&g_pih[layer - 1][t][group][rank][0][0])[tid];
        }

        float2 aA0, aA1, aA2, aA3, aB0, aB1, aB2, aB3;
        if (kc == 0) {
            float bA = smem[OFF_BIAS + rp], bB = smem[OFF_BIAS + rp + 64];
            aA0 = aA1 = aA2 = aA3 = make_float2(bA, bA);
            aB0 = aB1 = aB2 = aB3 = make_float2(bB, bB);
        } else {
            aA0 = aA1 = aA2 = aA3 = make_float2(0.f, 0.f);
            aB0 = aB1 = aB2 = aB3 = aA0;
        }

        if (layer == 0 && kc == 0) {
            float4 xlo, xhi;
            if (t < TIN) {
                const float4* xp = (const float4*)&smem[OFF_X + t * 8];
                xlo = xp[0]; xhi = xp[1];
            } else {
                if (tid == 0) { while (ld_acq(&g_xdone[group][t - TIN]) < 1) {} }
                asm volatile("bar.sync 2, 64;" ::: "memory");
                const float4* xp = (const float4*)&g_xpred[t - TIN][group][0];
                xlo = xp[0]; xhi = xp[1];
            }
            float wxA = smem[OFF_WX + rp], wxB = smem[OFF_WX + rp + 64];
            float2 q01 = make_float2(xlo.x, xlo.y), q23 = make_float2(xlo.z, xlo.w);
            float2 q45 = make_float2(xhi.x, xhi.y), q67 = make_float2(xhi.z, xhi.w);
            aA0 = ffma2(wxA, q01, aA0); aA1 = ffma2(wxA, q23, aA1);
            aA2 = ffma2(wxA, q45, aA2); aA3 = ffma2(wxA, q67, aA3);
            aB0 = ffma2(wxB, q01, aB0); aB1 = ffma2(wxB, q23, aB1);
            aB2 = ffma2(wxB, q45, aB2); aB3 = ffma2(wxB, q67, aB3);
        }

        if (t > 0) bar_wait(bar, (t - 1) & 1);

        {
            const float4* wA4 = (const float4*)&smem[OFF_W + rp * 132 + kc * 16];
            const float4* wB4 = (const float4*)&smem[OFF_W + (rp + 64) * 132 + kc * 16];
            const float4* h4  = (const float4*)&smem[OFF_HH + (par ^ 1) * 1024 + kc * 16 * 8];
            #pragma unroll
            for (int j4 = 0; j4 < 4; j4++) GEMV_J4(j4)
        }
        {
            float2* pp = sP + rp * 34 + kc * 4;
            *(float4*)(pp)     = make_float4(aA0.x, aA0.y, aA1.x, aA1.y);
            *(float4*)(pp + 2) = make_float4(aA2.x, aA2.y, aA3.x, aA3.y);
            float2* pq = pp + 64 * 34;
            *(float4*)(pq)     = make_float4(aB0.x, aB0.y, aB1.x, aB1.y);
            *(float4*)(pq + 2) = make_float4(aB2.x, aB2.y, aB3.x, aB3.y);
        }
        if (layer > 0 && tid < 256) ((float4*)&smem[OFF_PIH])[tid] = pih;
        __syncthreads();

        if (tid < 128) {
            float2 gt[4];
            #pragma unroll
            for (int g = 0; g < 4; g++) {
                int row = g * 32 + au;
                const float2* pr = sP + row * 34 + abp;
                float2 s = pr[0];
                #pragma unroll
                for (int q = 1; q < 8; q++) { float2 v = pr[q * 4]; s.x += v.x; s.y += v.y; }
                if (layer > 0) {
                    float2 v = *(const float2*)&smem[OFF_PIH + row * 8 + abp * 2];
                    s.x += v.x; s.y += v.y;
                }
                gt[g] = s;
            }
            float2 ho;
            ho.x = act1(gt[0].x, gt[1].x, gt[2].x, gt[3].x, cst.x);
            ho.y = act1(gt[0].y, gt[1].y, gt[2].y, gt[3].y, cst.y);
            int uo = rank * 32 + au;
            *(float2*)&smem[OFF_HH + par * 1024 + uo * 8 + abp * 2] = ho;
            uint32_t hoff = sbase + (uint32_t)(OFF_HH + par * 1024 + uo * 8 + abp * 2) * 4;
            #pragma unroll
            for (int j = 0; j < CSIZE; j++)
                if (j != rank) st_cluster_f2(mapa_u32(hoff, j), ho);
            if (layer < 4)
                *(float2*)&g_h[layer][t][group][uo][abp * 2] = ho;
        }
        __syncthreads();
        if (tid == NTHR - 1) {
            #pragma unroll
            for (int j = 0; j < CSIZE; j++)
                if (j != rank) mbar_arrive_rel(mapa_u32(bar, j));
            if (layer < 4) red_rel(&g_cnt[group][layer][t]);
        }

        if (layer == 4 && rank == 0 && t >= 511) {
            int m = t - 511;
            bar_wait(bar, t & 1);
            const float* h4h = &smem[OFF_HH + par * 1024];
            float* z2 = &smem[OFF_G];
            {
                int j = tid & 127, bh = tid >> 7;
                float2 acc = make_float2(b1[j], b1[j]);
                for (int k = 0; k < HID; k++) {
                    float2 hv = *(const float2*)&h4h[k * 8 + bh * 2];
                    float w = W1[k * HID + j];
                    acc.x += w * fmaxf(hv.x, 0.0f);
                    acc.y += w * fmaxf(hv.y, 0.0f);
                }
                z2[(2 * bh)     * 128 + j] = fmaxf(acc.x, 0.0f);
                z2[(2 * bh + 1) * 128 + j] = fmaxf(acc.y, 0.0f);
            }
            __syncthreads();
            if (tid < 128) {
                int b = tid >> 4, oo = tid & 15;
                float s = b2[oo];
                #pragma unroll 8
                for (int k = 0; k < HID; k++) s += z2[b * 128 + k] * W2[k * 16 + oo];
                if (m == 2) {
                    out[(b0 + b) * 18 + 2 + oo] = s;
                } else if (oo == 15) {
                    out[(b0 + b) * 18 + m] = s;
                    g_xpred[m][group][b] = s;
                }
            }
            __syncthreads();
            if (m < 2 && tid == 0) red_rel(&g_xdone[group][m]);
        }
    }

    asm volatile("barrier.cluster.arrive.aligned;" ::: "memory");
    asm volatile("barrier.cluster.wait.aligned;" ::: "memory");
}

extern "C" void kernel_launch(void* const* d_in, const int* in_sizes, int n_in,
                              void* d_out, int out_size) {
    const float* x    = (const float*)d_in[0];
    const float* Wih0 = (const float*)d_in[2];
    const float* Wihr = (const float*)d_in[3];
    const float* Whh  = (const float*)d_in[4];
    const float* bih  = (const float*)d_in[5];
    const float* bhh  = (const float*)d_in[6];
    const float* W1   = (const float*)d_in[7];
    const float* b1   = (const float*)d_in[8];
    const float* W2   = (const float*)d_in[9];
    const float* b2   = (const float*)d_in[10];
    float* out = (float*)d_out;

    static bool attr_set = false;
    if (!attr_set) {
        cudaFuncSetAttribute(lstm_main, cudaFuncAttributeMaxDynamicSharedMemorySize, SMEM_BYTES);
        attr_set = true;
    }

    zero_flags_kernel<<<17, 512>>>();

    cudaLaunchConfig_t cfg = {};
    cfg.gridDim = dim3(GRID_N, 1, 1);
    cfg.blockDim = dim3(NTHR, 1, 1);
    cfg.dynamicSmemBytes = SMEM_BYTES;
    cfg.stream = 0;
    cudaLaunchAttribute attrs[1];
    attrs[0].id = cudaLaunchAttributeClusterDimension;
    attrs[0].val.clusterDim.x = CSIZE;
    attrs[0].val.clusterDim.y = 1;
    attrs[0].val.clusterDim.z = 1;
    cfg.attrs = attrs;
    cfg.numAttrs = 1;
    cudaLaunchKernelEx(&cfg, lstm_main, x, Wih0, Wihr, Whh, bih, bhh,
                       W1, b1, W2, b2, out);
}